// round 13
// baseline (speedup 1.0000x reference)
#include <cuda_runtime.h>
#include <cstdint>

#define T_STEPS 1000
#define BATCH   2048
#define FEAT    40
#define H1      8
#define H2      6
#define G1      32

#define CT      10
#define NCHUNK  (T_STEPS / CT)      // 100
#define SITES   (CT * FEAT / 4)     // 100 float4 per chunk per element

typedef unsigned long long u64;

// ---------------- helpers ----------------
__device__ __forceinline__ u64 pack2(float x, float y) {
    u64 r; asm("mov.b64 %0, {%1, %2};" : "=l"(r) : "f"(x), "f"(y)); return r;
}
__device__ __forceinline__ void unpack2(u64 v, float& x, float& y) {
    asm("mov.b64 {%0, %1}, %2;" : "=f"(x), "=f"(y) : "l"(v));
}
__device__ __forceinline__ u64 fma2(u64 a, u64 b, u64 c) {
    u64 d; asm("fma.rn.f32x2 %0, %1, %2, %3;" : "=l"(d) : "l"(a), "l"(b), "l"(c)); return d;
}
__device__ __forceinline__ u64 mul2(u64 a, u64 b) {
    u64 d; asm("mul.rn.f32x2 %0, %1, %2;" : "=l"(d) : "l"(a), "l"(b)); return d;
}
__device__ __forceinline__ u64 add2(u64 a, u64 b) {
    u64 d; asm("add.rn.f32x2 %0, %1, %2;" : "=l"(d) : "l"(a), "l"(b)); return d;
}
__device__ __forceinline__ u64 scale2(u64 v, float s) {
    float a, b; unpack2(v, a, b); return pack2(a * s, b * s);
}
__device__ __forceinline__ float hadd2(u64 v) {
    float a, b; unpack2(v, a, b); return a + b;
}
__device__ __forceinline__ float tanha(float x) {
    float r; asm("tanh.approx.f32 %0, %1;" : "=f"(r) : "f"(x)); return r;
}
__device__ __forceinline__ float shflf(float v, int src) {
    return __shfl_sync(0xffffffffu, v, src & 31);
}
__device__ __forceinline__ float shflx(float v, int m) {
    return __shfl_xor_sync(0xffffffffu, v, m);
}
__device__ __forceinline__ uint32_t smem_u32(const void* p) {
    uint32_t a;
    asm("{ .reg .u64 t; cvta.to.shared.u64 t, %1; cvt.u32.u64 %0, t; }" : "=r"(a) : "l"(p));
    return a;
}
__device__ __forceinline__ void cp_async16(uint32_t saddr, const void* gaddr) {
    asm volatile("cp.async.cg.shared.global [%0], [%1], 16;" :: "r"(saddr), "l"(gaddr));
}
__device__ __forceinline__ void cp_commit() {
    asm volatile("cp.async.commit_group;" ::: "memory");
}
template <int N>
__device__ __forceinline__ void cp_wait() {
    asm volatile("cp.async.wait_group %0;" :: "n"(N) : "memory");
}
#define BAR64() asm volatile("bar.sync 0, 64;" ::: "memory")

// ============================================================================
// consumer step on a batch PAIR (f32x2 halves = elements e0,e1).
// slab shs[2][24] of u64 pairs: [0..7]=h1, [8..15]=x2, [16..21]=h2
// L1 gates at lanes: i 0-7 | f 8-15 | g 16-23 | o 24-31  (c1 on lanes 8-15)
// L2 gates at lanes: i 0-5 | f 8-13 | g 16-21 | o 24-29  (c2 on lanes 8-13)
// ============================================================================
template <int RD>
__device__ __forceinline__ void rec_step2(
    u64 en2, int lane, u64 gvalp,
    u64 (*shs)[24],
    const u64* __restrict__ w1d, const u64* __restrict__ wi2d,
    const u64* __restrict__ wh2d, u64 bias2d,
    float cn1, float ca1, float cn2, float ca2,
    u64& c1, u64& c2)
{
    constexpr int WR = RD ^ 1;

    const ulonglong2* hp = reinterpret_cast<const ulonglong2*>(&shs[RD][0]);
    ulonglong2 h01 = hp[0], h23 = hp[1], h45 = hp[2], h67 = hp[3];  // h1 pairs
    ulonglong2 x01 = hp[4], x23 = hp[5], x45 = hp[6], x67 = hp[7];  // x2 pairs
    ulonglong2 q01 = hp[8], q23 = hp[9], q45 = hp[10];              // h2 pairs

    // layer1: g1 = gval + h1 . w1  (both elements at once)
    u64 A = fma2(h01.x, w1d[0], gvalp);
    u64 B = mul2(h01.y, w1d[1]);
    A = fma2(h23.x, w1d[2], A);
    B = fma2(h23.y, w1d[3], B);
    A = fma2(h45.x, w1d[4], A);
    B = fma2(h45.y, w1d[5], B);
    A = fma2(h67.x, w1d[6], A);
    B = fma2(h67.y, w1d[7], B);
    u64 g1p = add2(A, B);

    // layer2: g2 = bias2 + x2 . wi2 + h2 . wh2
    u64 P = fma2(x01.x, wi2d[0], bias2d);
    u64 Q = mul2(x01.y, wi2d[1]);
    u64 R = mul2(x23.x, wi2d[2]);
    P = fma2(x23.y, wi2d[3], P);
    Q = fma2(x45.x, wi2d[4], Q);
    R = fma2(x45.y, wi2d[5], R);
    P = fma2(x67.x, wi2d[6], P);
    Q = fma2(x67.y, wi2d[7], Q);
    R = fma2(q01.x, wh2d[0], R);
    P = fma2(q01.y, wh2d[1], P);
    Q = fma2(q23.x, wh2d[2], Q);
    R = fma2(q23.y, wh2d[3], R);
    P = fma2(q45.x, wh2d[4], P);
    Q = fma2(q45.y, wh2d[5], Q);
    u64 g2p = add2(add2(P, Q), R);

    float g1x, g1y; unpack2(g1p, g1x, g1y);
    float g2x, g2y; unpack2(g2p, g2x, g2y);
    float a1x = fmaf(cn1, tanha(g1x), ca1);
    float a1y = fmaf(cn1, tanha(g1y), ca1);
    float a2x = fmaf(cn2, tanha(g2x), ca2);
    float a2y = fmaf(cn2, tanha(g2y), ca2);

    // XOR gathers (per half)
    float s1x = shflx(a1x, 16), s1y = shflx(a1y, 16);
    float s2x = shflx(a2x, 16), s2y = shflx(a2y, 16);
    float p1x = a1x * s1x, p1y = a1y * s1y;
    float p2x = a2x * s2x, p2y = a2y * s2y;
    float t1x = shflx(p1x, 8), t1y = shflx(p1y, 8);
    float t2x = shflx(p2x, 8), t2y = shflx(p2y, 8);

    // state owners: lanes 8-15 hold a1=f, s1=o
    c1 = fma2(pack2(a1x, a1y), c1, pack2(t1x, t1y));
    float c1x, c1y; unpack2(c1, c1x, c1y);
    float h1vx = s1x * tanha(c1x), h1vy = s1y * tanha(c1y);
    float x2vx = tanha(h1vx),      x2vy = tanha(h1vy);

    // lanes 8-13 hold a2=f2, s2=o2
    c2 = mul2(en2, fma2(pack2(a2x, a2y), c2, pack2(t2x, t2y)));
    float c2x, c2y; unpack2(c2, c2x, c2y);
    float h2vx = s2x * tanha(c2x), h2vy = s2y * tanha(c2y);

    if (lane >= 8 && lane < 16) {
        shs[WR][lane - 8] = pack2(h1vx, h1vy);   // h1 pair
        shs[WR][lane]     = pack2(x2vx, x2vy);   // x2 pair
    }
    if (lane >= 8 && lane < 14) shs[WR][8 + lane] = pack2(h2vx, h2vy);
    __syncwarp();
}

// producer: gates for one chunk, BOTH elements; lane=(l,h), rows 2p+h.
// dstq[r][l] = (vA_e0, vA_e1, vB_e0, vB_e1)  -> one STS.128 per row.
__device__ __forceinline__ void produce_chunk2(
    const float (*s0)[FEAT], const float (*s1)[FEAT],
    float4 (*dstq)[16],
    int l, int h,
    const u64* __restrict__ wA, const u64* __restrict__ wB,
    float bA, float bB)
{
    float vA0[5], vB0[5], vA1[5], vB1[5];
#pragma unroll
    for (int p = 0; p < 5; p++) {
        int r = 2 * p + h;
        const ulonglong2* xr = reinterpret_cast<const ulonglong2*>(&s0[r][0]);
        u64 a0 = pack2(bA, 0.f), a1 = 0ull;
        u64 b0 = pack2(bB, 0.f), b1 = 0ull;
#pragma unroll
        for (int q = 0; q < FEAT / 4; q++) {
            ulonglong2 v = xr[q];
            a0 = fma2(wA[2 * q],     v.x, a0);
            a1 = fma2(wA[2 * q + 1], v.y, a1);
            b0 = fma2(wB[2 * q],     v.x, b0);
            b1 = fma2(wB[2 * q + 1], v.y, b1);
        }
        vA0[p] = hadd2(add2(a0, a1));
        vB0[p] = hadd2(add2(b0, b1));
    }
#pragma unroll
    for (int p = 0; p < 5; p++) {
        int r = 2 * p + h;
        const ulonglong2* xr = reinterpret_cast<const ulonglong2*>(&s1[r][0]);
        u64 a0 = pack2(bA, 0.f), a1 = 0ull;
        u64 b0 = pack2(bB, 0.f), b1 = 0ull;
#pragma unroll
        for (int q = 0; q < FEAT / 4; q++) {
            ulonglong2 v = xr[q];
            a0 = fma2(wA[2 * q],     v.x, a0);
            a1 = fma2(wA[2 * q + 1], v.y, a1);
            b0 = fma2(wB[2 * q],     v.x, b0);
            b1 = fma2(wB[2 * q + 1], v.y, b1);
        }
        vA1[p] = hadd2(add2(a0, a1));
        vB1[p] = hadd2(add2(b0, b1));
    }
#pragma unroll
    for (int p = 0; p < 5; p++) {
        int r = 2 * p + h;
        dstq[r][l] = make_float4(vA0[p], vA1[p], vB0[p], vB1[p]);  // STS.128
    }
}

// ============================================================================
// fused kernel: 1 block = 2 batch elements, 2 warps.
// warp 0: paired consumer. warp 1: paired producer.
// ============================================================================
__global__ void __launch_bounds__(64)
fused_pc(const float* __restrict__ x,
         const float* __restrict__ W_ih1,
         const float* __restrict__ W_hh1,
         const float* __restrict__ b_ih1,
         const float* __restrict__ b_hh1,
         const float* __restrict__ W_ih2,
         const float* __restrict__ W_hh2,
         const float* __restrict__ b_ih2,
         const float* __restrict__ b_hh2,
         const float* __restrict__ W_fc,
         const float* __restrict__ b_fc,
         float* __restrict__ out) {
    __shared__ __align__(16) float4 sgate[2][CT][16];    // [buf][t][l]: (A0,A1,B0,B1)
    __shared__ __align__(16) float  sx[2][2][CT][FEAT];  // [elem][buf] x staging
    __shared__ __align__(16) u64    shs[2][24];          // paired hidden slabs

    int tid  = threadIdx.x;
    int lane = tid & 31;
    int wid  = tid >> 5;
    int e0   = blockIdx.x * 2;

    if (wid == 1) {
        // ======================= PRODUCER (both elements) =====================
        int l = lane & 15, h = lane >> 4;
        int gA = l, gB = l + 16;
        float cmA = 0.5f;
        float cmB = (l < 8) ? 1.0f : 0.5f;

        u64 wA[FEAT / 2], wB[FEAT / 2];
        {
            const u64* wra = reinterpret_cast<const u64*>(W_ih1 + gA * FEAT);
            const u64* wrb = reinterpret_cast<const u64*>(W_ih1 + gB * FEAT);
#pragma unroll
            for (int p = 0; p < FEAT / 2; p++) {
                wA[p] = scale2(wra[p], cmA);
                wB[p] = scale2(wrb[p], cmB);
            }
        }
        float bA = cmA * (b_ih1[gA] + b_hh1[gA]);
        float bB = cmB * (b_ih1[gB] + b_hh1[gB]);

        const float4* xb0 = reinterpret_cast<const float4*>(x + (size_t)e0 * T_STEPS * FEAT);
        const float4* xb1 = reinterpret_cast<const float4*>(x + (size_t)(e0 + 1) * T_STEPS * FEAT);
        uint32_t sa[2][2];
        sa[0][0] = smem_u32(&sx[0][0][0][0]);
        sa[0][1] = smem_u32(&sx[0][1][0][0]);
        sa[1][0] = smem_u32(&sx[1][0][0][0]);
        sa[1][1] = smem_u32(&sx[1][1][0][0]);

        // issue chunks 0,1 (both elements per commit group)
#pragma unroll
        for (int i = 0; i < 4; i++) {
            int s = lane + 32 * i;
            if (s < SITES) { cp_async16(sa[0][0] + 16 * s, xb0 + s);
                             cp_async16(sa[1][0] + 16 * s, xb1 + s); }
        }
        cp_commit();
#pragma unroll
        for (int i = 0; i < 4; i++) {
            int s = lane + 32 * i;
            if (s < SITES) { cp_async16(sa[0][1] + 16 * s, xb0 + SITES + s);
                             cp_async16(sa[1][1] + 16 * s, xb1 + SITES + s); }
        }
        cp_commit();
        cp_wait<1>();
        __syncwarp();

        produce_chunk2(sx[0][0], sx[1][0], sgate[0], l, h, wA, wB, bA, bB);
        BAR64();

#pragma unroll 1
        for (int c = 0; c < NCHUNK; c++) {
            if (c + 1 < NCHUNK) {
                int c2i = (c + 2 < NCHUNK) ? c + 2 : NCHUNK - 1;
#pragma unroll
                for (int i = 0; i < 4; i++) {
                    int s = lane + 32 * i;
                    if (s < SITES) {
                        cp_async16(sa[0][c & 1] + 16 * s, xb0 + (size_t)c2i * SITES + s);
                        cp_async16(sa[1][c & 1] + 16 * s, xb1 + (size_t)c2i * SITES + s);
                    }
                }
                cp_commit();
                cp_wait<1>();      // chunk c+1 resident
                __syncwarp();

                produce_chunk2(sx[0][(c + 1) & 1], sx[1][(c + 1) & 1],
                               sgate[(c + 1) & 1], l, h, wA, wB, bA, bB);
            }
            BAR64();
        }
        cp_wait<0>();
    } else {
        // ======================= CONSUMER (paired) ============================
        bool t1c = ((lane >> 3) == 2);
        float cm1 = t1c ? 1.f : 0.5f, cn1 = t1c ? 1.f : 0.5f, ca1 = t1c ? 0.f : 0.5f;
        bool v2 = ((lane & 7) < 6) && (lane < 30);
        int g2i = lane - 2 * (lane >> 3);
        bool t2c = (lane >= 16 && lane < 22);
        float cm2 = t2c ? 1.f : 0.5f, cn2 = t2c ? 1.f : 0.5f, ca2 = t2c ? 0.f : 0.5f;

        // duplicated weights (same for both elements)
        u64 w1d[H1];
#pragma unroll
        for (int j = 0; j < H1; j++) {
            float w = cm1 * W_hh1[lane * H1 + j];
            w1d[j] = pack2(w, w);
        }
        u64 wi2d[H1], wh2d[H2], bias2d = 0ull;
#pragma unroll
        for (int j = 0; j < H1; j++) wi2d[j] = 0ull;
#pragma unroll
        for (int j = 0; j < H2; j++) wh2d[j] = 0ull;
        if (v2) {
#pragma unroll
            for (int j = 0; j < H1; j++) {
                float w = cm2 * W_ih2[g2i * H1 + j];
                wi2d[j] = pack2(w, w);
            }
#pragma unroll
            for (int j = 0; j < H2; j++) {
                float w = cm2 * W_hh2[g2i * H2 + j];
                wh2d[j] = pack2(w, w);
            }
            float bb = cm2 * (b_ih2[g2i] + b_hh2[g2i]);
            bias2d = pack2(bb, bb);
        }

        if (lane < 24) shs[1][lane] = 0ull;
        u64 c1 = 0ull, c2 = 0ull;
        BAR64();

        int gidx = (lane & 15) * 2 + (lane >> 4);       // u64 offset within [t]
        const u64 one2 = pack2(1.f, 1.f);

#pragma unroll 1
        for (int c = 0; c < NCHUNK; c++) {
            const u64* gr = reinterpret_cast<const u64*>(&sgate[c & 1][0][0]);
            u64 en0 = (c == 0) ? 0ull : one2;

            rec_step2<1>(en0,  lane, gr[0 * 32 + gidx], shs, w1d, wi2d, wh2d, bias2d,
                         cn1, ca1, cn2, ca2, c1, c2);
            rec_step2<0>(one2, lane, gr[1 * 32 + gidx], shs, w1d, wi2d, wh2d, bias2d,
                         cn1, ca1, cn2, ca2, c1, c2);
            rec_step2<1>(one2, lane, gr[2 * 32 + gidx], shs, w1d, wi2d, wh2d, bias2d,
                         cn1, ca1, cn2, ca2, c1, c2);
            rec_step2<0>(one2, lane, gr[3 * 32 + gidx], shs, w1d, wi2d, wh2d, bias2d,
                         cn1, ca1, cn2, ca2, c1, c2);
            rec_step2<1>(one2, lane, gr[4 * 32 + gidx], shs, w1d, wi2d, wh2d, bias2d,
                         cn1, ca1, cn2, ca2, c1, c2);
            rec_step2<0>(one2, lane, gr[5 * 32 + gidx], shs, w1d, wi2d, wh2d, bias2d,
                         cn1, ca1, cn2, ca2, c1, c2);
            rec_step2<1>(one2, lane, gr[6 * 32 + gidx], shs, w1d, wi2d, wh2d, bias2d,
                         cn1, ca1, cn2, ca2, c1, c2);
            rec_step2<0>(one2, lane, gr[7 * 32 + gidx], shs, w1d, wi2d, wh2d, bias2d,
                         cn1, ca1, cn2, ca2, c1, c2);
            rec_step2<1>(one2, lane, gr[8 * 32 + gidx], shs, w1d, wi2d, wh2d, bias2d,
                         cn1, ca1, cn2, ca2, c1, c2);
            rec_step2<0>(one2, lane, gr[9 * 32 + gidx], shs, w1d, wi2d, wh2d, bias2d,
                         cn1, ca1, cn2, ca2, c1, c2);
            BAR64();
        }

        // ---- epilogue: layer2(999) from shs[1] (x2(999), h2(998)), paired ----
        const ulonglong2* hp = reinterpret_cast<const ulonglong2*>(&shs[1][0]);
        ulonglong2 x01 = hp[4], x23 = hp[5], x45 = hp[6], x67 = hp[7];
        ulonglong2 q01 = hp[8], q23 = hp[9], q45 = hp[10];

        u64 P = fma2(x01.x, wi2d[0], bias2d);
        u64 Q = mul2(x01.y, wi2d[1]);
        u64 R = mul2(x23.x, wi2d[2]);
        P = fma2(x23.y, wi2d[3], P);
        Q = fma2(x45.x, wi2d[4], Q);
        R = fma2(x45.y, wi2d[5], R);
        P = fma2(x67.x, wi2d[6], P);
        Q = fma2(x67.y, wi2d[7], Q);
        R = fma2(q01.x, wh2d[0], R);
        P = fma2(q01.y, wh2d[1], P);
        Q = fma2(q23.x, wh2d[2], Q);
        R = fma2(q23.y, wh2d[3], R);
        P = fma2(q45.x, wh2d[4], P);
        Q = fma2(q45.y, wh2d[5], Q);
        u64 g2p = add2(add2(P, Q), R);

        float g2x, g2y; unpack2(g2p, g2x, g2y);
        float a2x = fmaf(cn2, tanha(g2x), ca2);
        float a2y = fmaf(cn2, tanha(g2y), ca2);
        float s2x = shflx(a2x, 16), s2y = shflx(a2y, 16);
        float p2x = a2x * s2x,      p2y = a2y * s2y;
        float t2x = shflx(p2x, 8),  t2y = shflx(p2y, 8);
        c2 = fma2(pack2(a2x, a2y), c2, pack2(t2x, t2y));   // lanes 8-13
        float c2x, c2y; unpack2(c2, c2x, c2y);
        float txx = tanha(s2x * tanha(c2x));   // tanh(h2(999)) elem 0
        float txy = tanha(s2y * tanha(c2y));   // elem 1

        float s0 = b_fc[0], s1v = b_fc[0];
#pragma unroll
        for (int j = 0; j < H2; j++) {
            float vx = shflf(txx, 8 + j);
            float vy = shflf(txy, 8 + j);
            float wf = W_fc[j];
            s0  = fmaf(vx, wf, s0);
            s1v = fmaf(vy, wf, s1v);
        }
        if (lane == 0) {
            out[e0]     = fmaf(0.5f, tanha(0.5f * s0),  0.5f);
            out[e0 + 1] = fmaf(0.5f, tanha(0.5f * s1v), 0.5f);
        }
    }
}

// ============================================================================
extern "C" void kernel_launch(void* const* d_in, const int* in_sizes, int n_in,
                              void* d_out, int out_size) {
    const float* x     = (const float*)d_in[0];
    const float* W_ih1 = (const float*)d_in[1];
    const float* W_hh1 = (const float*)d_in[2];
    const float* b_ih1 = (const float*)d_in[3];
    const float* b_hh1 = (const float*)d_in[4];
    const float* W_ih2 = (const float*)d_in[5];
    const float* W_hh2 = (const float*)d_in[6];
    const float* b_ih2 = (const float*)d_in[7];
    const float* b_hh2 = (const float*)d_in[8];
    const float* W_fc  = (const float*)d_in[9];
    const float* b_fc  = (const float*)d_in[10];
    float* out = (float*)d_out;

    fused_pc<<<BATCH / 2, 64>>>(x, W_ih1, W_hh1, b_ih1, b_hh1,
                                W_ih2, W_hh2, b_ih2, b_hh2, W_fc, b_fc, out);
}

// round 14
// speedup vs baseline: 1.1663x; 1.1663x over previous
#include <cuda_runtime.h>
#include <cstdint>

#define T_STEPS 1000
#define BATCH   2048
#define FEAT    40
#define H1      8
#define H2      6
#define G1      32

#define CT      10
#define NCHUNK  (T_STEPS / CT)      // 100
#define SITES   (CT * FEAT / 4)     // 100 float4 per chunk

typedef unsigned long long u64;

// ---------------- helpers ----------------
__device__ __forceinline__ u64 pack2(float x, float y) {
    u64 r; asm("mov.b64 %0, {%1, %2};" : "=l"(r) : "f"(x), "f"(y)); return r;
}
__device__ __forceinline__ void unpack2(u64 v, float& x, float& y) {
    asm("mov.b64 {%0, %1}, %2;" : "=f"(x), "=f"(y) : "l"(v));
}
__device__ __forceinline__ u64 fma2(u64 a, u64 b, u64 c) {
    u64 d; asm("fma.rn.f32x2 %0, %1, %2, %3;" : "=l"(d) : "l"(a), "l"(b), "l"(c)); return d;
}
__device__ __forceinline__ u64 mul2(u64 a, u64 b) {
    u64 d; asm("mul.rn.f32x2 %0, %1, %2;" : "=l"(d) : "l"(a), "l"(b)); return d;
}
__device__ __forceinline__ u64 add2(u64 a, u64 b) {
    u64 d; asm("add.rn.f32x2 %0, %1, %2;" : "=l"(d) : "l"(a), "l"(b)); return d;
}
__device__ __forceinline__ u64 scale2(u64 v, float s) {
    float a, b; unpack2(v, a, b); return pack2(a * s, b * s);
}
__device__ __forceinline__ float hadd2(u64 v) {
    float a, b; unpack2(v, a, b); return a + b;
}
__device__ __forceinline__ float tanha(float x) {
    float r; asm("tanh.approx.f32 %0, %1;" : "=f"(r) : "f"(x)); return r;
}
__device__ __forceinline__ float shflf(float v, int src) {
    return __shfl_sync(0xffffffffu, v, src & 31);
}
__device__ __forceinline__ float shflx(float v, int m) {
    return __shfl_xor_sync(0xffffffffu, v, m);
}
__device__ __forceinline__ uint32_t smem_u32(const void* p) {
    uint32_t a;
    asm("{ .reg .u64 t; cvta.to.shared.u64 t, %1; cvt.u32.u64 %0, t; }" : "=r"(a) : "l"(p));
    return a;
}
__device__ __forceinline__ void cp_async16(uint32_t saddr, const void* gaddr) {
    asm volatile("cp.async.cg.shared.global [%0], [%1], 16;" :: "r"(saddr), "l"(gaddr));
}
__device__ __forceinline__ void cp_commit() {
    asm volatile("cp.async.commit_group;" ::: "memory");
}
template <int N>
__device__ __forceinline__ void cp_wait() {
    asm volatile("cp.async.wait_group %0;" :: "n"(N) : "memory");
}
#define BAR64() asm volatile("bar.sync 0, 64;" ::: "memory")

// ============================================================================
// consumer step (R10 proven, verbatim): layer1(i) + layer2(i-1), XOR gathers.
// slab shs[2][24]: [0..7]=h1, [8..15]=x2, [16..21]=h2
// L1 gates at lanes: i 0-7 | f 8-15 | g 16-23 | o 24-31  (c1 on lanes 8-15)
// L2 gates at lanes: i 0-5 | f 8-13 | g 16-21 | o 24-29  (c2 on lanes 8-13)
// ============================================================================
template <int RD>
__device__ __forceinline__ void rec_step(
    float en, int lane, float gval,
    float (*shs)[24],
    const u64* __restrict__ w1p, const u64* __restrict__ wi2p,
    const u64* __restrict__ wh2p, u64 bias2p,
    float cn1, float ca1, float cn2, float ca2,
    float& c1, float& c2)
{
    constexpr int WR = RD ^ 1;

    const ulonglong2* hp = reinterpret_cast<const ulonglong2*>(&shs[RD][0]);
    ulonglong2 h01 = hp[0], h23 = hp[1];   // h1[0..7]
    ulonglong2 x01 = hp[2], x23 = hp[3];   // x2[0..7]
    ulonglong2 h2a = hp[4];                // h2[0..3]
    u64        h2b = reinterpret_cast<const u64*>(&shs[RD][0])[10];  // h2[4..5]

    // layer1: g1 = gval + h1 . w1
    u64 C = mul2(h01.x, w1p[0]);
    C = fma2(h01.y, w1p[1], C);
    u64 D = mul2(h23.x, w1p[2]);
    D = fma2(h23.y, w1p[3], D);
    float g1 = gval + hadd2(add2(C, D));

    // layer2: g2 = bias2 + x2 . wi2 + h2 . wh2
    u64 P = fma2(x01.x, wi2p[0], bias2p);
    u64 Q = mul2(x01.y, wi2p[1]);
    P = fma2(x23.x, wi2p[2], P);
    Q = fma2(x23.y, wi2p[3], Q);
    P = fma2(h2a.x, wh2p[0], P);
    Q = fma2(h2a.y, wh2p[1], Q);
    P = fma2(h2b,   wh2p[2], P);
    float g2 = hadd2(add2(P, Q));

    float a1 = fmaf(cn1, tanha(g1), ca1);
    float a2 = fmaf(cn2, tanha(g2), ca2);

    // XOR gathers
    float s1 = shflx(a1, 16);
    float s2 = shflx(a2, 16);
    float p1 = a1 * s1;
    float p2 = a2 * s2;
    float t1 = shflx(p1, 8);     // lanes 8-15 <- i*g (L1)
    float t2 = shflx(p2, 8);     // lanes 8-13 <- i*g (L2)

    // state owners: lanes 8-15 hold a1=f, s1=o
    c1 = fmaf(a1, c1, t1);
    float h1v = s1 * tanha(c1);
    float x2v = tanha(h1v);

    // lanes 8-13 hold a2=f2, s2=o2
    c2 = en * fmaf(a2, c2, t2);
    float h2v = s2 * tanha(c2);

    if (lane >= 8 && lane < 16) {
        shs[WR][lane - 8] = h1v;   // h1 slot
        shs[WR][lane]     = x2v;   // x2 slot
    }
    if (lane >= 8 && lane < 14) shs[WR][8 + lane] = h2v;   // h2 slot 16+(lane-8)
    __syncwarp();
}

// ============================================================================
// producer chunk: ROW-MAJOR. All 32 lanes process the same row (broadcast
// LDS = 1 wavefront); lane = gate. Each lane holds only its gate's weights.
// ============================================================================
__device__ __forceinline__ void produce_chunk(
    const float (*src)[FEAT], float (*dstg)[G1],
    int lane, const u64* __restrict__ w2, float bias)
{
#pragma unroll
    for (int r = 0; r < CT; r++) {
        const ulonglong2* xr = reinterpret_cast<const ulonglong2*>(&src[r][0]);
        u64 a = pack2(bias, 0.f), b = 0ull;
#pragma unroll
        for (int q = 0; q < FEAT / 4; q++) {
            ulonglong2 v = xr[q];                 // broadcast LDS.128 (1 wf)
            a = fma2(w2[2 * q],     v.x, a);
            b = fma2(w2[2 * q + 1], v.y, b);
        }
        dstg[r][lane] = hadd2(add2(a, b));        // STS.32, 128B, 1 wf
    }
}

// ============================================================================
// fused producer/consumer kernel: 1 block = 1 batch element, 2 warps.
// ============================================================================
__global__ void __launch_bounds__(64)
fused_pc(const float* __restrict__ x,
         const float* __restrict__ W_ih1,
         const float* __restrict__ W_hh1,
         const float* __restrict__ b_ih1,
         const float* __restrict__ b_hh1,
         const float* __restrict__ W_ih2,
         const float* __restrict__ W_hh2,
         const float* __restrict__ b_ih2,
         const float* __restrict__ b_hh2,
         const float* __restrict__ W_fc,
         const float* __restrict__ b_fc,
         float* __restrict__ out) {
    __shared__ __align__(16) float sgate[2][CT][G1];   // flat gate ring
    __shared__ __align__(16) float sx[2][CT][FEAT];    // x staging (cp.async)
    __shared__ __align__(16) float shs[2][24];         // hidden slabs

    int tid  = threadIdx.x;
    int lane = tid & 31;
    int wid  = tid >> 5;
    int b    = blockIdx.x;

    if (wid == 1) {
        // ======================= PRODUCER (row-major, lane = gate) ===========
        float cm = (lane >= 16 && lane < 24) ? 1.0f : 0.5f;   // g-gates: tanh

        u64 w2[FEAT / 2];
        {
            const u64* wr = reinterpret_cast<const u64*>(W_ih1 + lane * FEAT);
#pragma unroll
            for (int p = 0; p < FEAT / 2; p++) w2[p] = scale2(wr[p], cm);
        }
        float bias = cm * (b_ih1[lane] + b_hh1[lane]);

        const float4* xb = reinterpret_cast<const float4*>(x + (size_t)b * T_STEPS * FEAT);
        uint32_t sx0 = smem_u32(&sx[0][0][0]);
        uint32_t sx1 = smem_u32(&sx[1][0][0]);

        // issue chunks 0,1
#pragma unroll
        for (int i = 0; i < 4; i++) {
            int s = lane + 32 * i;
            if (s < SITES) cp_async16(sx0 + 16 * s, xb + s);
        }
        cp_commit();
#pragma unroll
        for (int i = 0; i < 4; i++) {
            int s = lane + 32 * i;
            if (s < SITES) cp_async16(sx1 + 16 * s, xb + SITES + s);
        }
        cp_commit();
        cp_wait<1>();
        __syncwarp();

        produce_chunk(sx[0], sgate[0], lane, w2, bias);
        BAR64();

#pragma unroll 1
        for (int c = 0; c < NCHUNK; c++) {
            if (c + 1 < NCHUNK) {
                int c2i = (c + 2 < NCHUNK) ? c + 2 : NCHUNK - 1;
                uint32_t dst = (c & 1) ? sx1 : sx0;
#pragma unroll
                for (int i = 0; i < 4; i++) {
                    int s = lane + 32 * i;
                    if (s < SITES) cp_async16(dst + 16 * s, xb + (size_t)c2i * SITES + s);
                }
                cp_commit();
                cp_wait<1>();      // chunk c+1 resident
                __syncwarp();

                produce_chunk(sx[(c + 1) & 1], sgate[(c + 1) & 1], lane, w2, bias);
            }
            BAR64();
        }
        cp_wait<0>();
    } else {
        // ======================= CONSUMER (R10 verbatim) ======================
        bool t1c = ((lane >> 3) == 2);
        float cm1 = t1c ? 1.f : 0.5f, cn1 = t1c ? 1.f : 0.5f, ca1 = t1c ? 0.f : 0.5f;
        bool v2 = ((lane & 7) < 6) && (lane < 30);
        int g2i = lane - 2 * (lane >> 3);
        bool t2c = (lane >= 16 && lane < 22);
        float cm2 = t2c ? 1.f : 0.5f, cn2 = t2c ? 1.f : 0.5f, ca2 = t2c ? 0.f : 0.5f;

        u64 w1p[H1 / 2];
#pragma unroll
        for (int j = 0; j < H1 / 2; j++)
            w1p[j] = pack2(cm1 * W_hh1[lane * H1 + 2 * j], cm1 * W_hh1[lane * H1 + 2 * j + 1]);

        u64 wi2p[H1 / 2], wh2p[H2 / 2], bias2p = 0ull;
#pragma unroll
        for (int j = 0; j < H1 / 2; j++) wi2p[j] = 0ull;
#pragma unroll
        for (int j = 0; j < H2 / 2; j++) wh2p[j] = 0ull;
        if (v2) {
#pragma unroll
            for (int j = 0; j < H1 / 2; j++)
                wi2p[j] = pack2(cm2 * W_ih2[g2i * H1 + 2 * j], cm2 * W_ih2[g2i * H1 + 2 * j + 1]);
#pragma unroll
            for (int j = 0; j < H2 / 2; j++)
                wh2p[j] = pack2(cm2 * W_hh2[g2i * H2 + 2 * j], cm2 * W_hh2[g2i * H2 + 2 * j + 1]);
            bias2p = pack2(cm2 * (b_ih2[g2i] + b_hh2[g2i]), 0.f);
        }

        if (lane < 24) shs[1][lane] = 0.f;
        float c1 = 0.f, c2 = 0.f;
        BAR64();

#pragma unroll 1
        for (int c = 0; c < NCHUNK; c++) {
            const float* gr = &sgate[c & 1][0][0];
            float en0 = (c == 0) ? 0.f : 1.f;

            rec_step<1>(en0, lane, gr[0 * G1 + lane], shs, w1p, wi2p, wh2p, bias2p,
                        cn1, ca1, cn2, ca2, c1, c2);
            rec_step<0>(1.f, lane, gr[1 * G1 + lane], shs, w1p, wi2p, wh2p, bias2p,
                        cn1, ca1, cn2, ca2, c1, c2);
            rec_step<1>(1.f, lane, gr[2 * G1 + lane], shs, w1p, wi2p, wh2p, bias2p,
                        cn1, ca1, cn2, ca2, c1, c2);
            rec_step<0>(1.f, lane, gr[3 * G1 + lane], shs, w1p, wi2p, wh2p, bias2p,
                        cn1, ca1, cn2, ca2, c1, c2);
            rec_step<1>(1.f, lane, gr[4 * G1 + lane], shs, w1p, wi2p, wh2p, bias2p,
                        cn1, ca1, cn2, ca2, c1, c2);
            rec_step<0>(1.f, lane, gr[5 * G1 + lane], shs, w1p, wi2p, wh2p, bias2p,
                        cn1, ca1, cn2, ca2, c1, c2);
            rec_step<1>(1.f, lane, gr[6 * G1 + lane], shs, w1p, wi2p, wh2p, bias2p,
                        cn1, ca1, cn2, ca2, c1, c2);
            rec_step<0>(1.f, lane, gr[7 * G1 + lane], shs, w1p, wi2p, wh2p, bias2p,
                        cn1, ca1, cn2, ca2, c1, c2);
            rec_step<1>(1.f, lane, gr[8 * G1 + lane], shs, w1p, wi2p, wh2p, bias2p,
                        cn1, ca1, cn2, ca2, c1, c2);
            rec_step<0>(1.f, lane, gr[9 * G1 + lane], shs, w1p, wi2p, wh2p, bias2p,
                        cn1, ca1, cn2, ca2, c1, c2);
            BAR64();
        }

        // ---- epilogue: layer2(999) from shs[1] (x2(999), h2(998)) ----
        const ulonglong2* hp = reinterpret_cast<const ulonglong2*>(&shs[1][0]);
        ulonglong2 x01 = hp[2], x23 = hp[3], h2a = hp[4];
        u64 h2b = reinterpret_cast<const u64*>(&shs[1][0])[10];

        u64 P = fma2(x01.x, wi2p[0], bias2p);
        u64 Q = mul2(x01.y, wi2p[1]);
        P = fma2(x23.x, wi2p[2], P);
        Q = fma2(x23.y, wi2p[3], Q);
        P = fma2(h2a.x, wh2p[0], P);
        Q = fma2(h2a.y, wh2p[1], Q);
        P = fma2(h2b,   wh2p[2], P);
        float g2 = hadd2(add2(P, Q));

        float a2 = fmaf(cn2, tanha(g2), ca2);
        float s2 = shflx(a2, 16);
        float p2 = a2 * s2;
        float t2 = shflx(p2, 8);
        c2 = fmaf(a2, c2, t2);                 // lanes 8-13
        float tx = tanha(s2 * tanha(c2));      // tanh(h2(999)) at lanes 8-13

        float s = b_fc[0];
#pragma unroll
        for (int j = 0; j < H2; j++)
            s = fmaf(shflf(tx, 8 + j), W_fc[j], s);
        if (lane == 0)
            out[b] = fmaf(0.5f, tanha(0.5f * s), 0.5f);
    }
}

// ============================================================================
extern "C" void kernel_launch(void* const* d_in, const int* in_sizes, int n_in,
                              void* d_out, int out_size) {
    const float* x     = (const float*)d_in[0];
    const float* W_ih1 = (const float*)d_in[1];
    const float* W_hh1 = (const float*)d_in[2];
    const float* b_ih1 = (const float*)d_in[3];
    const float* b_hh1 = (const float*)d_in[4];
    const float* W_ih2 = (const float*)d_in[5];
    const float* W_hh2 = (const float*)d_in[6];
    const float* b_ih2 = (const float*)d_in[7];
    const float* b_hh2 = (const float*)d_in[8];
    const float* W_fc  = (const float*)d_in[9];
    const float* b_fc  = (const float*)d_in[10];
    float* out = (float*)d_out;

    fused_pc<<<BATCH, 64>>>(x, W_ih1, W_hh1, b_ih1, b_hh1,
                            W_ih2, W_hh2, b_ih2, b_hh2, W_fc, b_fc, out);
}

// round 15
// speedup vs baseline: 1.1940x; 1.0237x over previous
#include <cuda_runtime.h>
#include <cstdint>

#define T_STEPS 1000
#define BATCH   2048
#define FEAT    40
#define H1      8
#define H2      6
#define G1      32

#define CT      10
#define NCHUNK  (T_STEPS / CT)      // 100
#define SITES   (CT * FEAT / 4)     // 100 float4 per chunk

typedef unsigned long long u64;

// ---------------- helpers ----------------
__device__ __forceinline__ u64 pack2(float x, float y) {
    u64 r; asm("mov.b64 %0, {%1, %2};" : "=l"(r) : "f"(x), "f"(y)); return r;
}
__device__ __forceinline__ void unpack2(u64 v, float& x, float& y) {
    asm("mov.b64 {%0, %1}, %2;" : "=f"(x), "=f"(y) : "l"(v));
}
__device__ __forceinline__ u64 fma2(u64 a, u64 b, u64 c) {
    u64 d; asm("fma.rn.f32x2 %0, %1, %2, %3;" : "=l"(d) : "l"(a), "l"(b), "l"(c)); return d;
}
__device__ __forceinline__ u64 mul2(u64 a, u64 b) {
    u64 d; asm("mul.rn.f32x2 %0, %1, %2;" : "=l"(d) : "l"(a), "l"(b)); return d;
}
__device__ __forceinline__ u64 add2(u64 a, u64 b) {
    u64 d; asm("add.rn.f32x2 %0, %1, %2;" : "=l"(d) : "l"(a), "l"(b)); return d;
}
__device__ __forceinline__ u64 scale2(u64 v, float s) {
    float a, b; unpack2(v, a, b); return pack2(a * s, b * s);
}
__device__ __forceinline__ float hadd2(u64 v) {
    float a, b; unpack2(v, a, b); return a + b;
}
__device__ __forceinline__ float tanha(float x) {
    float r; asm("tanh.approx.f32 %0, %1;" : "=f"(r) : "f"(x)); return r;
}
__device__ __forceinline__ float shflf(float v, int src) {
    return __shfl_sync(0xffffffffu, v, src & 31);
}
__device__ __forceinline__ float shflx(float v, int m) {
    return __shfl_xor_sync(0xffffffffu, v, m);
}
__device__ __forceinline__ uint32_t smem_u32(const void* p) {
    uint32_t a;
    asm("{ .reg .u64 t; cvta.to.shared.u64 t, %1; cvt.u32.u64 %0, t; }" : "=r"(a) : "l"(p));
    return a;
}
__device__ __forceinline__ void cp_async16(uint32_t saddr, const void* gaddr) {
    asm volatile("cp.async.cg.shared.global [%0], [%1], 16;" :: "r"(saddr), "l"(gaddr));
}
__device__ __forceinline__ void cp_commit() {
    asm volatile("cp.async.commit_group;" ::: "memory");
}
template <int N>
__device__ __forceinline__ void cp_wait() {
    asm volatile("cp.async.wait_group %0;" :: "n"(N) : "memory");
}
#define BAR64() asm volatile("bar.sync 0, 64;" ::: "memory")

// ============================================================================
// consumer step (R10/R14 proven, verbatim): layer1(i) + layer2(i-1).
// slab shs[2][24]: [0..7]=h1, [8..15]=x2, [16..21]=h2
// L1 gates at lanes: i 0-7 | f 8-15 | g 16-23 | o 24-31  (c1 on lanes 8-15)
// L2 gates at lanes: i 0-5 | f 8-13 | g 16-21 | o 24-29  (c2 on lanes 8-13)
// ============================================================================
template <int RD>
__device__ __forceinline__ void rec_step(
    float en, int lane, float gval,
    float (*shs)[24],
    const u64* __restrict__ w1p, const u64* __restrict__ wi2p,
    const u64* __restrict__ wh2p, u64 bias2p,
    float cn1, float ca1, float cn2, float ca2,
    float& c1, float& c2)
{
    constexpr int WR = RD ^ 1;

    const ulonglong2* hp = reinterpret_cast<const ulonglong2*>(&shs[RD][0]);
    ulonglong2 h01 = hp[0], h23 = hp[1];   // h1[0..7]
    ulonglong2 x01 = hp[2], x23 = hp[3];   // x2[0..7]
    ulonglong2 h2a = hp[4];                // h2[0..3]
    u64        h2b = reinterpret_cast<const u64*>(&shs[RD][0])[10];  // h2[4..5]

    // layer1: g1 = gval + h1 . w1
    u64 C = mul2(h01.x, w1p[0]);
    C = fma2(h01.y, w1p[1], C);
    u64 D = mul2(h23.x, w1p[2]);
    D = fma2(h23.y, w1p[3], D);
    float g1 = gval + hadd2(add2(C, D));

    // layer2: g2 = bias2 + x2 . wi2 + h2 . wh2
    u64 P = fma2(x01.x, wi2p[0], bias2p);
    u64 Q = mul2(x01.y, wi2p[1]);
    P = fma2(x23.x, wi2p[2], P);
    Q = fma2(x23.y, wi2p[3], Q);
    P = fma2(h2a.x, wh2p[0], P);
    Q = fma2(h2a.y, wh2p[1], Q);
    P = fma2(h2b,   wh2p[2], P);
    float g2 = hadd2(add2(P, Q));

    float a1 = fmaf(cn1, tanha(g1), ca1);
    float a2 = fmaf(cn2, tanha(g2), ca2);

    // XOR gathers
    float s1 = shflx(a1, 16);
    float s2 = shflx(a2, 16);
    float p1 = a1 * s1;
    float p2 = a2 * s2;
    float t1 = shflx(p1, 8);     // lanes 8-15 <- i*g (L1)
    float t2 = shflx(p2, 8);     // lanes 8-13 <- i*g (L2)

    // state owners: lanes 8-15 hold a1=f, s1=o
    c1 = fmaf(a1, c1, t1);
    float h1v = s1 * tanha(c1);
    float x2v = tanha(h1v);

    // lanes 8-13 hold a2=f2, s2=o2
    c2 = en * fmaf(a2, c2, t2);
    float h2v = s2 * tanha(c2);

    if (lane >= 8 && lane < 16) {
        shs[WR][lane - 8] = h1v;   // h1 slot
        shs[WR][lane]     = x2v;   // x2 slot
    }
    if (lane >= 8 && lane < 14) shs[WR][8 + lane] = h2v;   // h2 slot 16+(lane-8)
    __syncwarp();
}

// ============================================================================
// producer chunk: SPLIT-K G=2. lane = (l = gate pair 0-15, h = feature half).
// Each lane: gates (l, l+16) over features [20h, 20h+20) -> 40 weight regs.
// x loads: 5 LDS.128/row, 2 conflict-free addresses (1 wf each).
// One shfl_xor(16) exchanges cross partials; lane stores gate l+16h.
// ============================================================================
__device__ __forceinline__ void produce_chunk(
    const float (*src)[FEAT], float (*dstg)[G1],
    int l, int h,
    const u64* __restrict__ wA, const u64* __restrict__ wB,
    u64 seedA, u64 seedB)
{
#pragma unroll
    for (int r = 0; r < CT; r++) {
        const ulonglong2* xr = reinterpret_cast<const ulonglong2*>(&src[r][20 * h]);
        ulonglong2 v0 = xr[0], v1 = xr[1], v2 = xr[2], v3 = xr[3], v4 = xr[4];

        u64 a0 = fma2(wA[0], v0.x, seedA);
        u64 a1 = mul2(wA[1], v0.y);
        u64 b0 = fma2(wB[0], v0.x, seedB);
        u64 b1 = mul2(wB[1], v0.y);
        a0 = fma2(wA[2], v1.x, a0);
        a1 = fma2(wA[3], v1.y, a1);
        b0 = fma2(wB[2], v1.x, b0);
        b1 = fma2(wB[3], v1.y, b1);
        a0 = fma2(wA[4], v2.x, a0);
        a1 = fma2(wA[5], v2.y, a1);
        b0 = fma2(wB[4], v2.x, b0);
        b1 = fma2(wB[5], v2.y, b1);
        a0 = fma2(wA[6], v3.x, a0);
        a1 = fma2(wA[7], v3.y, a1);
        b0 = fma2(wB[6], v3.x, b0);
        b1 = fma2(wB[7], v3.y, b1);
        a0 = fma2(wA[8], v4.x, a0);
        a1 = fma2(wA[9], v4.y, a1);
        b0 = fma2(wB[8], v4.x, b0);
        b1 = fma2(wB[9], v4.y, b1);

        float pA = hadd2(add2(a0, a1));
        float pB = hadd2(add2(b0, b1));

        // exchange: send what the xor-partner needs, receive our missing half
        float send = h ? pA : pB;
        float recv = shflx(send, 16);
        float full = (h ? pB : pA) + recv;

        dstg[r][l + 16 * h] = full;     // 32 consecutive words: 1 wf
    }
}

// ============================================================================
// fused producer/consumer kernel: 1 block = 1 batch element, 2 warps.
// ============================================================================
__global__ void __launch_bounds__(64)
fused_pc(const float* __restrict__ x,
         const float* __restrict__ W_ih1,
         const float* __restrict__ W_hh1,
         const float* __restrict__ b_ih1,
         const float* __restrict__ b_hh1,
         const float* __restrict__ W_ih2,
         const float* __restrict__ W_hh2,
         const float* __restrict__ b_ih2,
         const float* __restrict__ b_hh2,
         const float* __restrict__ W_fc,
         const float* __restrict__ b_fc,
         float* __restrict__ out) {
    __shared__ __align__(16) float sgate[2][CT][G1];   // flat gate ring
    __shared__ __align__(16) float sx[2][CT][FEAT];    // x staging (cp.async)
    __shared__ __align__(16) float shs[2][24];         // hidden slabs

    int tid  = threadIdx.x;
    int lane = tid & 31;
    int wid  = tid >> 5;
    int b    = blockIdx.x;

    if (wid == 1) {
        // ============ PRODUCER (split-K G=2: lane = (l, h)) ============
        int l = lane & 15, h = lane >> 4;
        int gA = l, gB = l + 16;
        float cmA = 0.5f;                     // gates 0..15: sigmoid
        float cmB = (l < 8) ? 1.0f : 0.5f;    // 16..23 tanh, 24..31 sigmoid

        u64 wA[10], wB[10];
        {
            const u64* wra = reinterpret_cast<const u64*>(W_ih1 + gA * FEAT + 20 * h);
            const u64* wrb = reinterpret_cast<const u64*>(W_ih1 + gB * FEAT + 20 * h);
#pragma unroll
            for (int p = 0; p < 10; p++) {
                wA[p] = scale2(wra[p], cmA);
                wB[p] = scale2(wrb[p], cmB);
            }
        }
        // bias seeds only on h==0 lanes (avoid double count after xor-add)
        u64 seedA = (h == 0) ? pack2(cmA * (b_ih1[gA] + b_hh1[gA]), 0.f) : 0ull;
        u64 seedB = (h == 0) ? pack2(cmB * (b_ih1[gB] + b_hh1[gB]), 0.f) : 0ull;

        const float4* xb = reinterpret_cast<const float4*>(x + (size_t)b * T_STEPS * FEAT);
        uint32_t sx0 = smem_u32(&sx[0][0][0]);
        uint32_t sx1 = smem_u32(&sx[1][0][0]);

        // issue chunks 0,1
#pragma unroll
        for (int i = 0; i < 4; i++) {
            int s = lane + 32 * i;
            if (s < SITES) cp_async16(sx0 + 16 * s, xb + s);
        }
        cp_commit();
#pragma unroll
        for (int i = 0; i < 4; i++) {
            int s = lane + 32 * i;
            if (s < SITES) cp_async16(sx1 + 16 * s, xb + SITES + s);
        }
        cp_commit();
        cp_wait<1>();
        __syncwarp();

        produce_chunk(sx[0], sgate[0], l, h, wA, wB, seedA, seedB);
        BAR64();

#pragma unroll 1
        for (int c = 0; c < NCHUNK; c++) {
            if (c + 1 < NCHUNK) {
                int c2i = (c + 2 < NCHUNK) ? c + 2 : NCHUNK - 1;
                uint32_t dst = (c & 1) ? sx1 : sx0;
#pragma unroll
                for (int i = 0; i < 4; i++) {
                    int s = lane + 32 * i;
                    if (s < SITES) cp_async16(dst + 16 * s, xb + (size_t)c2i * SITES + s);
                }
                cp_commit();
                cp_wait<1>();      // chunk c+1 resident
                __syncwarp();

                produce_chunk(sx[(c + 1) & 1], sgate[(c + 1) & 1], l, h, wA, wB,
                              seedA, seedB);
            }
            BAR64();
        }
        cp_wait<0>();
    } else {
        // ======================= CONSUMER (R14 verbatim) ======================
        bool t1c = ((lane >> 3) == 2);
        float cm1 = t1c ? 1.f : 0.5f, cn1 = t1c ? 1.f : 0.5f, ca1 = t1c ? 0.f : 0.5f;
        bool v2 = ((lane & 7) < 6) && (lane < 30);
        int g2i = lane - 2 * (lane >> 3);
        bool t2c = (lane >= 16 && lane < 22);
        float cm2 = t2c ? 1.f : 0.5f, cn2 = t2c ? 1.f : 0.5f, ca2 = t2c ? 0.f : 0.5f;

        u64 w1p[H1 / 2];
#pragma unroll
        for (int j = 0; j < H1 / 2; j++)
            w1p[j] = pack2(cm1 * W_hh1[lane * H1 + 2 * j], cm1 * W_hh1[lane * H1 + 2 * j + 1]);

        u64 wi2p[H1 / 2], wh2p[H2 / 2], bias2p = 0ull;
#pragma unroll
        for (int j = 0; j < H1 / 2; j++) wi2p[j] = 0ull;
#pragma unroll
        for (int j = 0; j < H2 / 2; j++) wh2p[j] = 0ull;
        if (v2) {
#pragma unroll
            for (int j = 0; j < H1 / 2; j++)
                wi2p[j] = pack2(cm2 * W_ih2[g2i * H1 + 2 * j], cm2 * W_ih2[g2i * H1 + 2 * j + 1]);
#pragma unroll
            for (int j = 0; j < H2 / 2; j++)
                wh2p[j] = pack2(cm2 * W_hh2[g2i * H2 + 2 * j], cm2 * W_hh2[g2i * H2 + 2 * j + 1]);
            bias2p = pack2(cm2 * (b_ih2[g2i] + b_hh2[g2i]), 0.f);
        }

        if (lane < 24) shs[1][lane] = 0.f;
        float c1 = 0.f, c2 = 0.f;
        BAR64();

#pragma unroll 1
        for (int c = 0; c < NCHUNK; c++) {
            const float* gr = &sgate[c & 1][0][0];
            float en0 = (c == 0) ? 0.f : 1.f;

            rec_step<1>(en0, lane, gr[0 * G1 + lane], shs, w1p, wi2p, wh2p, bias2p,
                        cn1, ca1, cn2, ca2, c1, c2);
            rec_step<0>(1.f, lane, gr[1 * G1 + lane], shs, w1p, wi2p, wh2p, bias2p,
                        cn1, ca1, cn2, ca2, c1, c2);
            rec_step<1>(1.f, lane, gr[2 * G1 + lane], shs, w1p, wi2p, wh2p, bias2p,
                        cn1, ca1, cn2, ca2, c1, c2);
            rec_step<0>(1.f, lane, gr[3 * G1 + lane], shs, w1p, wi2p, wh2p, bias2p,
                        cn1, ca1, cn2, ca2, c1, c2);
            rec_step<1>(1.f, lane, gr[4 * G1 + lane], shs, w1p, wi2p, wh2p, bias2p,
                        cn1, ca1, cn2, ca2, c1, c2);
            rec_step<0>(1.f, lane, gr[5 * G1 + lane], shs, w1p, wi2p, wh2p, bias2p,
                        cn1, ca1, cn2, ca2, c1, c2);
            rec_step<1>(1.f, lane, gr[6 * G1 + lane], shs, w1p, wi2p, wh2p, bias2p,
                        cn1, ca1, cn2, ca2, c1, c2);
            rec_step<0>(1.f, lane, gr[7 * G1 + lane], shs, w1p, wi2p, wh2p, bias2p,
                        cn1, ca1, cn2, ca2, c1, c2);
            rec_step<1>(1.f, lane, gr[8 * G1 + lane], shs, w1p, wi2p, wh2p, bias2p,
                        cn1, ca1, cn2, ca2, c1, c2);
            rec_step<0>(1.f, lane, gr[9 * G1 + lane], shs, w1p, wi2p, wh2p, bias2p,
                        cn1, ca1, cn2, ca2, c1, c2);
            BAR64();
        }

        // ---- epilogue: layer2(999) from shs[1] (x2(999), h2(998)) ----
        const ulonglong2* hp = reinterpret_cast<const ulonglong2*>(&shs[1][0]);
        ulonglong2 x01 = hp[2], x23 = hp[3], h2a = hp[4];
        u64 h2b = reinterpret_cast<const u64*>(&shs[1][0])[10];

        u64 P = fma2(x01.x, wi2p[0], bias2p);
        u64 Q = mul2(x01.y, wi2p[1]);
        P = fma2(x23.x, wi2p[2], P);
        Q = fma2(x23.y, wi2p[3], Q);
        P = fma2(h2a.x, wh2p[0], P);
        Q = fma2(h2a.y, wh2p[1], Q);
        P = fma2(h2b,   wh2p[2], P);
        float g2 = hadd2(add2(P, Q));

        float a2 = fmaf(cn2, tanha(g2), ca2);
        float s2 = shflx(a2, 16);
        float p2 = a2 * s2;
        float t2 = shflx(p2, 8);
        c2 = fmaf(a2, c2, t2);                 // lanes 8-13
        float tx = tanha(s2 * tanha(c2));      // tanh(h2(999)) at lanes 8-13

        float s = b_fc[0];
#pragma unroll
        for (int j = 0; j < H2; j++)
            s = fmaf(shflf(tx, 8 + j), W_fc[j], s);
        if (lane == 0)
            out[b] = fmaf(0.5f, tanha(0.5f * s), 0.5f);
    }
}

// ============================================================================
extern "C" void kernel_launch(void* const* d_in, const int* in_sizes, int n_in,
                              void* d_out, int out_size) {
    const float* x     = (const float*)d_in[0];
    const float* W_ih1 = (const float*)d_in[1];
    const float* W_hh1 = (const float*)d_in[2];
    const float* b_ih1 = (const float*)d_in[3];
    const float* b_hh1 = (const float*)d_in[4];
    const float* W_ih2 = (const float*)d_in[5];
    const float* W_hh2 = (const float*)d_in[6];
    const float* b_ih2 = (const float*)d_in[7];
    const float* b_hh2 = (const float*)d_in[8];
    const float* W_fc  = (const float*)d_in[9];
    const float* b_fc  = (const float*)d_in[10];
    float* out = (float*)d_out;

    fused_pc<<<BATCH, 64>>>(x, W_ih1, W_hh1, b_ih1, b_hh1,
                            W_ih2, W_hh2, b_ih2, b_hh2, W_fc, b_fc, out);
}

// round 16
// speedup vs baseline: 1.2056x; 1.0097x over previous
#include <cuda_runtime.h>
#include <cstdint>

#define T_STEPS 1000
#define BATCH   2048
#define FEAT    40
#define H1      8
#define H2      6
#define G1      32

#define CT      10
#define NCHUNK  (T_STEPS / CT)      // 100
#define SITES   (CT * FEAT / 4)     // 100 float4 per chunk

typedef unsigned long long u64;

// ---------------- helpers ----------------
__device__ __forceinline__ u64 pack2(float x, float y) {
    u64 r; asm("mov.b64 %0, {%1, %2};" : "=l"(r) : "f"(x), "f"(y)); return r;
}
__device__ __forceinline__ void unpack2(u64 v, float& x, float& y) {
    asm("mov.b64 {%0, %1}, %2;" : "=f"(x), "=f"(y) : "l"(v));
}
__device__ __forceinline__ u64 fma2(u64 a, u64 b, u64 c) {
    u64 d; asm("fma.rn.f32x2 %0, %1, %2, %3;" : "=l"(d) : "l"(a), "l"(b), "l"(c)); return d;
}
__device__ __forceinline__ u64 mul2(u64 a, u64 b) {
    u64 d; asm("mul.rn.f32x2 %0, %1, %2;" : "=l"(d) : "l"(a), "l"(b)); return d;
}
__device__ __forceinline__ u64 add2(u64 a, u64 b) {
    u64 d; asm("add.rn.f32x2 %0, %1, %2;" : "=l"(d) : "l"(a), "l"(b)); return d;
}
__device__ __forceinline__ u64 scale2(u64 v, float s) {
    float a, b; unpack2(v, a, b); return pack2(a * s, b * s);
}
__device__ __forceinline__ float hadd2(u64 v) {
    float a, b; unpack2(v, a, b); return a + b;
}
__device__ __forceinline__ float tanha(float x) {
    float r; asm("tanh.approx.f32 %0, %1;" : "=f"(r) : "f"(x)); return r;
}
__device__ __forceinline__ float shflf(float v, int src) {
    return __shfl_sync(0xffffffffu, v, src & 31);
}
__device__ __forceinline__ float shflx(float v, int m) {
    return __shfl_xor_sync(0xffffffffu, v, m);
}
__device__ __forceinline__ uint32_t smem_u32(const void* p) {
    uint32_t a;
    asm("{ .reg .u64 t; cvta.to.shared.u64 t, %1; cvt.u32.u64 %0, t; }" : "=r"(a) : "l"(p));
    return a;
}
__device__ __forceinline__ void cp_async16(uint32_t saddr, const void* gaddr) {
    asm volatile("cp.async.cg.shared.global [%0], [%1], 16;" :: "r"(saddr), "l"(gaddr));
}
__device__ __forceinline__ void cp_commit() {
    asm volatile("cp.async.commit_group;" ::: "memory");
}
template <int N>
__device__ __forceinline__ void cp_wait() {
    asm volatile("cp.async.wait_group %0;" :: "n"(N) : "memory");
}
#define BAR64() asm volatile("bar.sync 0, 64;" ::: "memory")

// ============================================================================
// consumer step (R10/R14/R15 proven, verbatim): layer1(i) + layer2(i-1).
// slab shs[2][24]: [0..7]=h1, [8..15]=x2, [16..21]=h2
// L1 gates at lanes: i 0-7 | f 8-15 | g 16-23 | o 24-31  (c1 on lanes 8-15)
// L2 gates at lanes: i 0-5 | f 8-13 | g 16-21 | o 24-29  (c2 on lanes 8-13)
// ============================================================================
template <int RD>
__device__ __forceinline__ void rec_step(
    float en, int lane, float gval,
    float (*shs)[24],
    const u64* __restrict__ w1p, const u64* __restrict__ wi2p,
    const u64* __restrict__ wh2p, u64 bias2p,
    float cn1, float ca1, float cn2, float ca2,
    float& c1, float& c2)
{
    constexpr int WR = RD ^ 1;

    const ulonglong2* hp = reinterpret_cast<const ulonglong2*>(&shs[RD][0]);
    ulonglong2 h01 = hp[0], h23 = hp[1];   // h1[0..7]
    ulonglong2 x01 = hp[2], x23 = hp[3];   // x2[0..7]
    ulonglong2 h2a = hp[4];                // h2[0..3]
    u64        h2b = reinterpret_cast<const u64*>(&shs[RD][0])[10];  // h2[4..5]

    // layer1: g1 = gval + h1 . w1
    u64 C = mul2(h01.x, w1p[0]);
    C = fma2(h01.y, w1p[1], C);
    u64 D = mul2(h23.x, w1p[2]);
    D = fma2(h23.y, w1p[3], D);
    float g1 = gval + hadd2(add2(C, D));

    // layer2: g2 = bias2 + x2 . wi2 + h2 . wh2
    u64 P = fma2(x01.x, wi2p[0], bias2p);
    u64 Q = mul2(x01.y, wi2p[1]);
    P = fma2(x23.x, wi2p[2], P);
    Q = fma2(x23.y, wi2p[3], Q);
    P = fma2(h2a.x, wh2p[0], P);
    Q = fma2(h2a.y, wh2p[1], Q);
    P = fma2(h2b,   wh2p[2], P);
    float g2 = hadd2(add2(P, Q));

    float a1 = fmaf(cn1, tanha(g1), ca1);
    float a2 = fmaf(cn2, tanha(g2), ca2);

    // XOR gathers
    float s1 = shflx(a1, 16);
    float s2 = shflx(a2, 16);
    float p1 = a1 * s1;
    float p2 = a2 * s2;
    float t1 = shflx(p1, 8);     // lanes 8-15 <- i*g (L1)
    float t2 = shflx(p2, 8);     // lanes 8-13 <- i*g (L2)

    // state owners: lanes 8-15 hold a1=f, s1=o
    c1 = fmaf(a1, c1, t1);
    float h1v = s1 * tanha(c1);
    float x2v = tanha(h1v);

    // lanes 8-13 hold a2=f2, s2=o2
    c2 = en * fmaf(a2, c2, t2);
    float h2v = s2 * tanha(c2);

    if (lane >= 8 && lane < 16) {
        shs[WR][lane - 8] = h1v;   // h1 slot
        shs[WR][lane]     = x2v;   // x2 slot
    }
    if (lane >= 8 && lane < 14) shs[WR][8 + lane] = h2v;   // h2 slot 16+(lane-8)
    __syncwarp();
}

// ============================================================================
// producer chunk: SPLIT-K G=2 (R15). lane = (l = gate pair, h = feature half).
// Bias now a single scalar added after the cross-half exchange (reg diet).
// ============================================================================
__device__ __forceinline__ void produce_chunk(
    const float (*src)[FEAT], float (*dstg)[G1],
    int l, int h,
    const u64* __restrict__ wA, const u64* __restrict__ wB,
    float bias)
{
#pragma unroll
    for (int r = 0; r < CT; r++) {
        const ulonglong2* xr = reinterpret_cast<const ulonglong2*>(&src[r][20 * h]);
        ulonglong2 v0 = xr[0], v1 = xr[1], v2 = xr[2], v3 = xr[3], v4 = xr[4];

        u64 a0 = mul2(wA[0], v0.x);
        u64 a1 = mul2(wA[1], v0.y);
        u64 b0 = mul2(wB[0], v0.x);
        u64 b1 = mul2(wB[1], v0.y);
        a0 = fma2(wA[2], v1.x, a0);
        a1 = fma2(wA[3], v1.y, a1);
        b0 = fma2(wB[2], v1.x, b0);
        b1 = fma2(wB[3], v1.y, b1);
        a0 = fma2(wA[4], v2.x, a0);
        a1 = fma2(wA[5], v2.y, a1);
        b0 = fma2(wB[4], v2.x, b0);
        b1 = fma2(wB[5], v2.y, b1);
        a0 = fma2(wA[6], v3.x, a0);
        a1 = fma2(wA[7], v3.y, a1);
        b0 = fma2(wB[6], v3.x, b0);
        b1 = fma2(wB[7], v3.y, b1);
        a0 = fma2(wA[8], v4.x, a0);
        a1 = fma2(wA[9], v4.y, a1);
        b0 = fma2(wB[8], v4.x, b0);
        b1 = fma2(wB[9], v4.y, b1);

        float pA = hadd2(add2(a0, a1));
        float pB = hadd2(add2(b0, b1));

        // exchange: send what the xor-partner needs, receive our missing half
        float send = h ? pA : pB;
        float recv = shflx(send, 16);
        float full = (h ? pB : pA) + recv + bias;

        dstg[r][l + 16 * h] = full;     // 32 consecutive words: 1 wf
    }
}

// ============================================================================
// fused producer/consumer kernel: 1 block = 1 batch element, 2 warps.
// launch_bounds(64,14): full single-wave residency (14 blocks/SM).
// ============================================================================
__global__ void __launch_bounds__(64, 14)
fused_pc(const float* __restrict__ x,
         const float* __restrict__ W_ih1,
         const float* __restrict__ W_hh1,
         const float* __restrict__ b_ih1,
         const float* __restrict__ b_hh1,
         const float* __restrict__ W_ih2,
         const float* __restrict__ W_hh2,
         const float* __restrict__ b_ih2,
         const float* __restrict__ b_hh2,
         const float* __restrict__ W_fc,
         const float* __restrict__ b_fc,
         float* __restrict__ out) {
    __shared__ __align__(16) float sgate[2][CT][G1];   // flat gate ring
    __shared__ __align__(16) float sx[2][CT][FEAT];    // x staging (cp.async)
    __shared__ __align__(16) float shs[2][24];         // hidden slabs

    int tid  = threadIdx.x;
    int lane = tid & 31;
    int wid  = tid >> 5;
    int b    = blockIdx.x;

    if (wid == 1) {
        // ============ PRODUCER (split-K G=2: lane = (l, h)) ============
        int l = lane & 15, h = lane >> 4;
        int gA = l, gB = l + 16;
        float cmA = 0.5f;                     // gates 0..15: sigmoid
        float cmB = (l < 8) ? 1.0f : 0.5f;    // 16..23 tanh, 24..31 sigmoid

        u64 wA[10], wB[10];
        {
            const u64* wra = reinterpret_cast<const u64*>(W_ih1 + gA * FEAT + 20 * h);
            const u64* wrb = reinterpret_cast<const u64*>(W_ih1 + gB * FEAT + 20 * h);
#pragma unroll
            for (int p = 0; p < 10; p++) {
                wA[p] = scale2(wra[p], cmA);
                wB[p] = scale2(wrb[p], cmB);
            }
        }
        // single scalar bias per lane: this lane stores gate l+16h
        float bias = h ? (cmB * (b_ih1[gB] + b_hh1[gB]))
                       : (cmA * (b_ih1[gA] + b_hh1[gA]));

        const float4* xb = reinterpret_cast<const float4*>(x + (size_t)b * T_STEPS * FEAT);
        uint32_t sx0 = smem_u32(&sx[0][0][0]);
        uint32_t sx1 = smem_u32(&sx[1][0][0]);

        // issue chunks 0,1
#pragma unroll
        for (int i = 0; i < 4; i++) {
            int s = lane + 32 * i;
            if (s < SITES) cp_async16(sx0 + 16 * s, xb + s);
        }
        cp_commit();
#pragma unroll
        for (int i = 0; i < 4; i++) {
            int s = lane + 32 * i;
            if (s < SITES) cp_async16(sx1 + 16 * s, xb + SITES + s);
        }
        cp_commit();
        cp_wait<1>();
        __syncwarp();

        produce_chunk(sx[0], sgate[0], l, h, wA, wB, bias);
        BAR64();

#pragma unroll 1
        for (int c = 0; c < NCHUNK; c++) {
            if (c + 1 < NCHUNK) {
                int c2i = (c + 2 < NCHUNK) ? c + 2 : NCHUNK - 1;
                uint32_t dst = (c & 1) ? sx1 : sx0;
#pragma unroll
                for (int i = 0; i < 4; i++) {
                    int s = lane + 32 * i;
                    if (s < SITES) cp_async16(dst + 16 * s, xb + (size_t)c2i * SITES + s);
                }
                cp_commit();
                cp_wait<1>();      // chunk c+1 resident
                __syncwarp();

                produce_chunk(sx[(c + 1) & 1], sgate[(c + 1) & 1], l, h, wA, wB, bias);
            }
            BAR64();
        }
        cp_wait<0>();
    } else {
        // ======================= CONSUMER (R15 verbatim) ======================
        bool t1c = ((lane >> 3) == 2);
        float cm1 = t1c ? 1.f : 0.5f, cn1 = t1c ? 1.f : 0.5f, ca1 = t1c ? 0.f : 0.5f;
        bool v2 = ((lane & 7) < 6) && (lane < 30);
        int g2i = lane - 2 * (lane >> 3);
        bool t2c = (lane >= 16 && lane < 22);
        float cm2 = t2c ? 1.f : 0.5f, cn2 = t2c ? 1.f : 0.5f, ca2 = t2c ? 0.f : 0.5f;

        u64 w1p[H1 / 2];
#pragma unroll
        for (int j = 0; j < H1 / 2; j++)
            w1p[j] = pack2(cm1 * W_hh1[lane * H1 + 2 * j], cm1 * W_hh1[lane * H1 + 2 * j + 1]);

        u64 wi2p[H1 / 2], wh2p[H2 / 2], bias2p = 0ull;
#pragma unroll
        for (int j = 0; j < H1 / 2; j++) wi2p[j] = 0ull;
#pragma unroll
        for (int j = 0; j < H2 / 2; j++) wh2p[j] = 0ull;
        if (v2) {
#pragma unroll
            for (int j = 0; j < H1 / 2; j++)
                wi2p[j] = pack2(cm2 * W_ih2[g2i * H1 + 2 * j], cm2 * W_ih2[g2i * H1 + 2 * j + 1]);
#pragma unroll
            for (int j = 0; j < H2 / 2; j++)
                wh2p[j] = pack2(cm2 * W_hh2[g2i * H2 + 2 * j], cm2 * W_hh2[g2i * H2 + 2 * j + 1]);
            bias2p = pack2(cm2 * (b_ih2[g2i] + b_hh2[g2i]), 0.f);
        }

        if (lane < 24) shs[1][lane] = 0.f;
        float c1 = 0.f, c2 = 0.f;
        BAR64();

#pragma unroll 1
        for (int c = 0; c < NCHUNK; c++) {
            const float* gr = &sgate[c & 1][0][0];
            float en0 = (c == 0) ? 0.f : 1.f;

            rec_step<1>(en0, lane, gr[0 * G1 + lane], shs, w1p, wi2p, wh2p, bias2p,
                        cn1, ca1, cn2, ca2, c1, c2);
            rec_step<0>(1.f, lane, gr[1 * G1 + lane], shs, w1p, wi2p, wh2p, bias2p,
                        cn1, ca1, cn2, ca2, c1, c2);
            rec_step<1>(1.f, lane, gr[2 * G1 + lane], shs, w1p, wi2p, wh2p, bias2p,
                        cn1, ca1, cn2, ca2, c1, c2);
            rec_step<0>(1.f, lane, gr[3 * G1 + lane], shs, w1p, wi2p, wh2p, bias2p,
                        cn1, ca1, cn2, ca2, c1, c2);
            rec_step<1>(1.f, lane, gr[4 * G1 + lane], shs, w1p, wi2p, wh2p, bias2p,
                        cn1, ca1, cn2, ca2, c1, c2);
            rec_step<0>(1.f, lane, gr[5 * G1 + lane], shs, w1p, wi2p, wh2p, bias2p,
                        cn1, ca1, cn2, ca2, c1, c2);
            rec_step<1>(1.f, lane, gr[6 * G1 + lane], shs, w1p, wi2p, wh2p, bias2p,
                        cn1, ca1, cn2, ca2, c1, c2);
            rec_step<0>(1.f, lane, gr[7 * G1 + lane], shs, w1p, wi2p, wh2p, bias2p,
                        cn1, ca1, cn2, ca2, c1, c2);
            rec_step<1>(1.f, lane, gr[8 * G1 + lane], shs, w1p, wi2p, wh2p, bias2p,
                        cn1, ca1, cn2, ca2, c1, c2);
            rec_step<0>(1.f, lane, gr[9 * G1 + lane], shs, w1p, wi2p, wh2p, bias2p,
                        cn1, ca1, cn2, ca2, c1, c2);
            BAR64();
        }

        // ---- epilogue: layer2(999) from shs[1] (x2(999), h2(998)) ----
        const ulonglong2* hp = reinterpret_cast<const ulonglong2*>(&shs[1][0]);
        ulonglong2 x01 = hp[2], x23 = hp[3], h2a = hp[4];
        u64 h2b = reinterpret_cast<const u64*>(&shs[1][0])[10];

        u64 P = fma2(x01.x, wi2p[0], bias2p);
        u64 Q = mul2(x01.y, wi2p[1]);
        P = fma2(x23.x, wi2p[2], P);
        Q = fma2(x23.y, wi2p[3], Q);
        P = fma2(h2a.x, wh2p[0], P);
        Q = fma2(h2a.y, wh2p[1], Q);
        P = fma2(h2b,   wh2p[2], P);
        float g2 = hadd2(add2(P, Q));

        float a2 = fmaf(cn2, tanha(g2), ca2);
        float s2 = shflx(a2, 16);
        float p2 = a2 * s2;
        float t2 = shflx(p2, 8);
        c2 = fmaf(a2, c2, t2);                 // lanes 8-13
        float tx = tanha(s2 * tanha(c2));      // tanh(h2(999)) at lanes 8-13

        float s = b_fc[0];
#pragma unroll
        for (int j = 0; j < H2; j++)
            s = fmaf(shflf(tx, 8 + j), W_fc[j], s);
        if (lane == 0)
            out[b] = fmaf(0.5f, tanha(0.5f * s), 0.5f);
    }
}

// ============================================================================
extern "C" void kernel_launch(void* const* d_in, const int* in_sizes, int n_in,
                              void* d_out, int out_size) {
    const float* x     = (const float*)d_in[0];
    const float* W_ih1 = (const float*)d_in[1];
    const float* W_hh1 = (const float*)d_in[2];
    const float* b_ih1 = (const float*)d_in[3];
    const float* b_hh1 = (const float*)d_in[4];
    const float* W_ih2 = (const float*)d_in[5];
    const float* W_hh2 = (const float*)d_in[6];
    const float* b_ih2 = (const float*)d_in[7];
    const float* b_hh2 = (const float*)d_in[8];
    const float* W_fc  = (const float*)d_in[9];
    const float* b_fc  = (const float*)d_in[10];
    float* out = (float*)d_out;

    fused_pc<<<BATCH, 64>>>(x, W_ih1, W_hh1, b_ih1, b_hh1,
                            W_ih2, W_hh2, b_ih2, b_hh2, W_fc, b_fc, out);
}